// round 11
// baseline (speedup 1.0000x reference)
#include <cuda_runtime.h>
#include <math.h>

#define N_NODES 12288
#define F_IN    1433
#define E_EDGES 196608
#define H1      32
#define H2      16
#define C_OUT   7

// ---------------- scratch (static __device__, no allocations) ----------------
__device__ __align__(16) float g_xws[N_NODES * H1];  // dis[n] * (x @ W1)[n]
__device__ __align__(16) float g_h[N_NODES * H1];    // GCN output (post relu)
__device__ __align__(16) float g_agg[N_NODES * H1];  // SAGE neighbor sum
__device__ float g_dis[N_NODES];        // (1+deg)^-0.5
__device__ int   g_cnt_i[N_NODES];      // out-count over ei0 (SAGE denominator)
__device__ int   g_deg_i[N_NODES];      // in-count over ei1 (GCN degree, pre-self-loop)
__device__ int   g_off[N_NODES + 1];    // CSR row offsets (by r = ei0)
__device__ int   g_cur[N_NODES];        // placement cursors
__device__ int   g_csr[E_EDGES];        // CSR column indices (c = ei1)
__device__ int   g_is64;                // edge_index dtype flag

__device__ __forceinline__ int edge_at(const int* ei32, int is64, int idx) {
    if (is64) return __ldg(&ei32[2 * idx]);  // little-endian low word of int64
    return __ldg(&ei32[idx]);
}

// ---------------- K0: detect dtype of edge_index ----------------
__global__ void detect_kernel(const int* __restrict__ ei32) {
    if (threadIdx.x == 0 && blockIdx.x == 0) {
        int any = 0;
        for (int k = 0; k < 256; k++) any |= ei32[2 * k + 1];
        g_is64 = (any == 0) ? 1 : 0;
    }
}

// ---------------- K1: init counters ----------------
__global__ void init_kernel() {
    int idx = blockIdx.x * blockDim.x + threadIdx.x;
    if (idx < N_NODES) { g_cnt_i[idx] = 0; g_deg_i[idx] = 0; g_cur[idx] = 0; }
}

// ---------------- K2: degree / count histogram (int) ----------------
__global__ void hist_kernel(const int* __restrict__ ei32) {
    int e = blockIdx.x * blockDim.x + threadIdx.x;
    if (e < E_EDGES) {
        int is64 = g_is64;
        int r = edge_at(ei32, is64, e);             // edge_index[0][e]
        int c = edge_at(ei32, is64, E_EDGES + e);   // edge_index[1][e]
        if ((unsigned)r < N_NODES) atomicAdd(&g_cnt_i[r], 1);
        if ((unsigned)c < N_NODES) atomicAdd(&g_deg_i[c], 1);
    }
}

// ---------------- K3: exclusive scan of cnt -> CSR offsets (1 block) ----------------
__global__ __launch_bounds__(1024) void scan_kernel() {
    __shared__ int sp[1024];
    int t = threadIdx.x;
    int base = t * 12;                 // 1024*12 = 12288
    int local[12];
    int s = 0;
#pragma unroll
    for (int i = 0; i < 12; i++) { local[i] = s; s += g_cnt_i[base + i]; }
    sp[t] = s;
    __syncthreads();
    for (int off = 1; off < 1024; off <<= 1) {
        int v = (t >= off) ? sp[t - off] : 0;
        __syncthreads();
        sp[t] += v;
        __syncthreads();
    }
    int prefix = (t > 0) ? sp[t - 1] : 0;
#pragma unroll
    for (int i = 0; i < 12; i++) g_off[base + i] = prefix + local[i];
    if (t == 1023) g_off[N_NODES] = sp[1023];
}

// ---------------- K4: CSR placement ----------------
__global__ void place_kernel(const int* __restrict__ ei32) {
    int e = blockIdx.x * blockDim.x + threadIdx.x;
    if (e >= E_EDGES) return;
    int is64 = g_is64;
    int r = edge_at(ei32, is64, e);
    int c = edge_at(ei32, is64, E_EDGES + e);
    if ((unsigned)r < N_NODES) {
        c = min(max(c, 0), N_NODES - 1);
        int p = atomicAdd(&g_cur[r], 1);
        g_csr[g_off[r] + p] = c;
    }
}

// ---------------- K5: xw = x @ W1 ; epilogue writes g_xws = dis*xw and g_dis ----------
// BM=32, BK=64, 128 threads, thread tile 2 rows x 4 cols. grid = 384 blocks.
#define BM  32
#define BKT 64
__global__ __launch_bounds__(128)
void gemm_kernel(const float* __restrict__ x, const float* __restrict__ W1) {
    __shared__ float xs[BM][BKT + 1];   // 32 x 65
    __shared__ float ws[BKT][H1];       // 64 x 32 (rows 128B-aligned for LDS.128)

    const int rowBase = blockIdx.x * BM;
    const int tx = threadIdx.x & 7;     // col quad
    const int ty = threadIdx.x >> 3;    // row pair, 0..15
    const int ty2 = ty * 2;
    const int tx4 = tx * 4;

    float acc[2][4] = {};

    const int nT = (F_IN + BKT - 1) / BKT;  // 23
    for (int kt = 0; kt < nT; kt++) {
        const int kBase = kt * BKT;
        // xs: 32x64, 16 floats/thread, coalesced (lane -> consecutive k)
#pragma unroll
        for (int i = 0; i < 16; i++) {
            int idx = threadIdx.x + i * 128;
            int r = idx >> 6, k = idx & 63;
            int kg = kBase + k;
            xs[r][k] = (kg < F_IN) ? x[(size_t)(rowBase + r) * F_IN + kg] : 0.0f;
        }
        // ws: 64x32, 16 floats/thread, coalesced
#pragma unroll
        for (int i = 0; i < 16; i++) {
            int idx = threadIdx.x + i * 128;
            int kr = idx >> 5, c = idx & 31;
            int kg = kBase + kr;
            ws[kr][c] = (kg < F_IN) ? W1[(size_t)kg * H1 + c] : 0.0f;
        }
        __syncthreads();

#pragma unroll 16
        for (int k = 0; k < BKT; k++) {
            float a0 = xs[ty2 + 0][k];
            float a1 = xs[ty2 + 1][k];
            float4 b = *reinterpret_cast<const float4*>(&ws[k][tx4]);
            acc[0][0] += a0 * b.x; acc[0][1] += a0 * b.y; acc[0][2] += a0 * b.z; acc[0][3] += a0 * b.w;
            acc[1][0] += a1 * b.x; acc[1][1] += a1 * b.y; acc[1][2] += a1 * b.z; acc[1][3] += a1 * b.w;
        }
        __syncthreads();
    }

    // epilogue: dis = (1+deg)^-1/2 ; g_xws = dis * acc ; g_dis
#pragma unroll
    for (int i = 0; i < 2; i++) {
        int row = rowBase + ty2 + i;
        float dis = rsqrtf(1.0f + (float)g_deg_i[row]);
        if (tx == 0) g_dis[row] = dis;
#pragma unroll
        for (int j = 0; j < 4; j++)
            g_xws[(size_t)row * H1 + tx4 + j] = dis * acc[i][j];
    }
}

// ---------------- K6: GCN gather (warp/node): h = relu(dis[n]*(self + sum xws[c]) + b1) ----
__global__ __launch_bounds__(256)
void gcn_gather(const float* __restrict__ b1) {
    int t = blockIdx.x * blockDim.x + threadIdx.x;
    int node = t >> 5, lane = t & 31;
    if (node >= N_NODES) return;
    float acc = g_xws[(size_t)node * H1 + lane];   // self-loop term (dis[n]*xw[n])
    int s = g_off[node], e = g_off[node + 1];
    for (int base = s; base < e; base += 32) {
        int cj = (base + lane < e) ? g_csr[base + lane] : 0;
        int m = min(e - base, 32);
        for (int i = 0; i < m; i++) {
            int c = __shfl_sync(0xffffffffu, cj, i);
            acc += g_xws[(size_t)c * H1 + lane];
        }
    }
    g_h[(size_t)node * H1 + lane] = fmaxf(g_dis[node] * acc + b1[lane], 0.0f);
}

// ---------------- K7: SAGE gather (warp/node): agg[n] = sum h[c] ----------------
__global__ __launch_bounds__(256)
void sage_gather() {
    int t = blockIdx.x * blockDim.x + threadIdx.x;
    int node = t >> 5, lane = t & 31;
    if (node >= N_NODES) return;
    float acc = 0.0f;
    int s = g_off[node], e = g_off[node + 1];
    for (int base = s; base < e; base += 32) {
        int cj = (base + lane < e) ? g_csr[base + lane] : 0;
        int m = min(e - base, 32);
        for (int i = 0; i < m; i++) {
            int c = __shfl_sync(0xffffffffu, cj, i);
            acc += g_h[(size_t)c * H1 + lane];
        }
    }
    g_agg[(size_t)node * H1 + lane] = acc;
}

// ---------------- K8: head ----------------
__global__ __launch_bounds__(256)
void final_kernel(const float* __restrict__ Wl, const float* __restrict__ bl,
                  const float* __restrict__ Wr, const float* __restrict__ br,
                  const float* __restrict__ W3, const float* __restrict__ b3,
                  float* __restrict__ out) {
    __shared__ float sWl[H1 * H2], sWr[H1 * H2], sW3[H2 * C_OUT];
    __shared__ float sbl[H2], sbr[H2], sb3[C_OUT];
    for (int i = threadIdx.x; i < H1 * H2; i += 256) { sWl[i] = Wl[i]; sWr[i] = Wr[i]; }
    if (threadIdx.x < H2 * C_OUT) sW3[threadIdx.x] = W3[threadIdx.x];
    if (threadIdx.x < H2) { sbl[threadIdx.x] = bl[threadIdx.x]; sbr[threadIdx.x] = br[threadIdx.x]; }
    if (threadIdx.x < C_OUT) sb3[threadIdx.x] = b3[threadIdx.x];
    __syncthreads();

    int n = blockIdx.x * blockDim.x + threadIdx.x;
    if (n >= N_NODES) return;

    float h[H1], ag[H1];
    const float4* hp = (const float4*)&g_h[(size_t)n * H1];
    const float4* ap = (const float4*)&g_agg[(size_t)n * H1];
#pragma unroll
    for (int i = 0; i < H1 / 4; i++) {
        float4 v = hp[i];
        h[i * 4 + 0] = v.x; h[i * 4 + 1] = v.y; h[i * 4 + 2] = v.z; h[i * 4 + 3] = v.w;
        float4 a = ap[i];
        ag[i * 4 + 0] = a.x; ag[i * 4 + 1] = a.y; ag[i * 4 + 2] = a.z; ag[i * 4 + 3] = a.w;
    }
    float cnt = (float)g_cnt_i[n];
    float cs = (cnt > 0.0f) ? (1.0f / cnt) : 0.0f;
#pragma unroll
    for (int k = 0; k < H1; k++) ag[k] *= cs;

    float o[H2];
    float ss = 0.0f;
#pragma unroll
    for (int j = 0; j < H2; j++) {
        float v = sbl[j] + sbr[j];
#pragma unroll
        for (int k = 0; k < H1; k++)
            v += h[k] * sWl[k * H2 + j] + ag[k] * sWr[k * H2 + j];
        v = fmaxf(v, 0.0f);
        o[j] = v;
        ss += v * v;
    }
    float inv = 1.0f / (sqrtf(ss) + 1e-6f);
#pragma unroll
    for (int j = 0; j < H2; j++) o[j] *= inv;

    float lg[C_OUT];
    float m = -1e30f;
#pragma unroll
    for (int j = 0; j < C_OUT; j++) {
        float v = sb3[j];
#pragma unroll
        for (int k = 0; k < H2; k++) v += o[k] * sW3[k * C_OUT + j];
        lg[j] = v;
        m = fmaxf(m, v);
    }
    float es = 0.0f;
#pragma unroll
    for (int j = 0; j < C_OUT; j++) { lg[j] = expf(lg[j] - m); es += lg[j]; }
    float invs = 1.0f / es;
#pragma unroll
    for (int j = 0; j < C_OUT; j++) out[(size_t)n * C_OUT + j] = lg[j] * invs;
}

// ---------------- launch ----------------
extern "C" void kernel_launch(void* const* d_in, const int* in_sizes, int n_in,
                              void* d_out, int out_size) {
    const float* x  = (const float*)d_in[0];
    const int*   ei = (const int*)d_in[1];   // int32 or int64 (autodetected)
    const float* W1 = (const float*)d_in[2];
    const float* b1 = (const float*)d_in[3];
    const float* Wl = (const float*)d_in[4];
    const float* bl = (const float*)d_in[5];
    const float* Wr = (const float*)d_in[6];
    const float* br = (const float*)d_in[7];
    const float* W3 = (const float*)d_in[8];
    const float* b3 = (const float*)d_in[9];
    float* out = (float*)d_out;

    detect_kernel<<<1, 1>>>(ei);
    init_kernel<<<(N_NODES + 255) / 256, 256>>>();
    hist_kernel<<<(E_EDGES + 255) / 256, 256>>>(ei);
    scan_kernel<<<1, 1024>>>();
    place_kernel<<<(E_EDGES + 255) / 256, 256>>>(ei);
    gemm_kernel<<<N_NODES / BM, 128>>>(x, W1);           // 384 blocks
    gcn_gather<<<(N_NODES * 32) / 256, 256>>>(b1);       // 1536 blocks
    sage_gather<<<(N_NODES * 32) / 256, 256>>>();
    final_kernel<<<(N_NODES + 255) / 256, 256>>>(Wl, bl, Wr, br, W3, b3, out);
}

// round 12
// speedup vs baseline: 1.0273x; 1.0273x over previous
#include <cuda_runtime.h>
#include <math.h>

#define N_NODES 12288
#define F_IN    1433
#define E_EDGES 196608
#define H1      32
#define H2      16
#define C_OUT   7

// ---------------- scratch (static __device__, no allocations) ----------------
__device__ __align__(16) float g_xws[N_NODES * H1];  // dis[n] * (x @ W1)[n]
__device__ __align__(16) float g_h[N_NODES * H1];    // GCN output (post relu)
__device__ __align__(16) float g_agg[N_NODES * H1];  // SAGE neighbor sum
__device__ float g_dis[N_NODES];                 // (1+deg)^-0.5
__device__ __align__(16) int g_cnt_i[N_NODES];   // out-count over ei0 (SAGE denominator)
__device__ int   g_deg_i[N_NODES];               // in-count over ei1 (GCN degree, pre-self-loop)
__device__ int   g_off[N_NODES + 1];             // CSR row offsets (by r = ei0)
__device__ int   g_cur[N_NODES];                 // placement cursors
__device__ int   g_csr[E_EDGES];                 // CSR column indices (c = ei1)
__device__ int   g_is64;                         // edge_index dtype flag

__device__ __forceinline__ int edge_at(const int* ei32, int is64, int idx) {
    if (is64) return __ldg(&ei32[2 * idx]);  // little-endian low word of int64
    return __ldg(&ei32[idx]);
}

// ---------------- K0: init counters + detect dtype (fused) ----------------
__global__ void init_kernel(const int* __restrict__ ei32) {
    int idx = blockIdx.x * blockDim.x + threadIdx.x;
    if (idx < N_NODES) { g_cnt_i[idx] = 0; g_deg_i[idx] = 0; g_cur[idx] = 0; }
    if (idx == 0) {
        // int64 values < 2^31 => odd 32-bit words all zero; int32 data: random.
        int any = 0;
        for (int k = 0; k < 256; k++) any |= ei32[2 * k + 1];
        g_is64 = (any == 0) ? 1 : 0;
    }
}

// ---------------- K1: degree / count histogram (int) ----------------
__global__ void hist_kernel(const int* __restrict__ ei32) {
    int e = blockIdx.x * blockDim.x + threadIdx.x;
    if (e < E_EDGES) {
        int is64 = g_is64;
        int r = edge_at(ei32, is64, e);             // edge_index[0][e]
        int c = edge_at(ei32, is64, E_EDGES + e);   // edge_index[1][e]
        if ((unsigned)r < N_NODES) atomicAdd(&g_cnt_i[r], 1);
        if ((unsigned)c < N_NODES) atomicAdd(&g_deg_i[c], 1);
    }
}

// ---------------- K2: exclusive scan of cnt -> CSR offsets (1 block, shfl-based) ----
__global__ __launch_bounds__(1024) void scan_kernel() {
    __shared__ int wsum[32];
    __shared__ int wexcl[32];
    int t = threadIdx.x, lane = t & 31, wid = t >> 5;
    int4 a = *reinterpret_cast<const int4*>(&g_cnt_i[t * 12]);
    int4 b = *reinterpret_cast<const int4*>(&g_cnt_i[t * 12 + 4]);
    int4 c = *reinterpret_cast<const int4*>(&g_cnt_i[t * 12 + 8]);
    int v[12] = {a.x, a.y, a.z, a.w, b.x, b.y, b.z, b.w, c.x, c.y, c.z, c.w};
    int pre[12];
    int s = 0;
#pragma unroll
    for (int i = 0; i < 12; i++) { pre[i] = s; s += v[i]; }
    int inc = s;
#pragma unroll
    for (int d = 1; d < 32; d <<= 1) {
        int u = __shfl_up_sync(0xffffffffu, inc, d);
        if (lane >= d) inc += u;
    }
    if (lane == 31) wsum[wid] = inc;
    __syncthreads();
    if (wid == 0) {
        int w = wsum[lane];
        int winc = w;
#pragma unroll
        for (int d = 1; d < 32; d <<= 1) {
            int u = __shfl_up_sync(0xffffffffu, winc, d);
            if (lane >= d) winc += u;
        }
        wexcl[lane] = winc - w;
    }
    __syncthreads();
    int base = wexcl[wid] + (inc - s);  // exclusive prefix of this thread
#pragma unroll
    for (int i = 0; i < 12; i++) g_off[t * 12 + i] = base + pre[i];
    if (t == 1023) g_off[N_NODES] = base + s;
}

// ---------------- K3: xw = x @ W1 ; epilogue writes g_xws = dis*xw and g_dis ----------
// BM=32, BK=64, 128 threads, thread tile 2 rows x 4 cols. grid = 384 blocks.
#define BM  32
#define BKT 64
__global__ __launch_bounds__(128)
void gemm_kernel(const float* __restrict__ x, const float* __restrict__ W1) {
    __shared__ float xs[BM][BKT + 1];   // 32 x 65
    __shared__ float ws[BKT][H1];       // 64 x 32 (rows 128B for LDS.128)

    const int rowBase = blockIdx.x * BM;
    const int tx = threadIdx.x & 7;     // col quad
    const int ty = threadIdx.x >> 3;    // row pair, 0..15
    const int ty2 = ty * 2;
    const int tx4 = tx * 4;

    float acc[2][4] = {};

    const int nT = (F_IN + BKT - 1) / BKT;  // 23
    for (int kt = 0; kt < nT; kt++) {
        const int kBase = kt * BKT;
#pragma unroll
        for (int i = 0; i < 16; i++) {
            int idx = threadIdx.x + i * 128;
            int r = idx >> 6, k = idx & 63;
            int kg = kBase + k;
            xs[r][k] = (kg < F_IN) ? x[(size_t)(rowBase + r) * F_IN + kg] : 0.0f;
        }
#pragma unroll
        for (int i = 0; i < 16; i++) {
            int idx = threadIdx.x + i * 128;
            int kr = idx >> 5, c = idx & 31;
            int kg = kBase + kr;
            ws[kr][c] = (kg < F_IN) ? W1[(size_t)kg * H1 + c] : 0.0f;
        }
        __syncthreads();

#pragma unroll 16
        for (int k = 0; k < BKT; k++) {
            float a0 = xs[ty2 + 0][k];
            float a1 = xs[ty2 + 1][k];
            float4 b = *reinterpret_cast<const float4*>(&ws[k][tx4]);
            acc[0][0] += a0 * b.x; acc[0][1] += a0 * b.y; acc[0][2] += a0 * b.z; acc[0][3] += a0 * b.w;
            acc[1][0] += a1 * b.x; acc[1][1] += a1 * b.y; acc[1][2] += a1 * b.z; acc[1][3] += a1 * b.w;
        }
        __syncthreads();
    }

    // epilogue: dis = (1+deg)^-1/2 ; g_xws = dis * acc ; g_dis
#pragma unroll
    for (int i = 0; i < 2; i++) {
        int row = rowBase + ty2 + i;
        float dis = rsqrtf(1.0f + (float)g_deg_i[row]);
        if (tx == 0) g_dis[row] = dis;
#pragma unroll
        for (int j = 0; j < 4; j++)
            g_xws[(size_t)row * H1 + tx4 + j] = dis * acc[i][j];
    }
}

// ---------------- K4: CSR placement ----------------
__global__ void place_kernel(const int* __restrict__ ei32) {
    int e = blockIdx.x * blockDim.x + threadIdx.x;
    if (e >= E_EDGES) return;
    int is64 = g_is64;
    int r = edge_at(ei32, is64, e);
    int c = edge_at(ei32, is64, E_EDGES + e);
    if ((unsigned)r < N_NODES) {
        c = min(max(c, 0), N_NODES - 1);
        int p = atomicAdd(&g_cur[r], 1);
        g_csr[g_off[r] + p] = c;
    }
}

// ---------------- K5: GCN gather (warp/node): h = relu(dis[n]*(self + sum xws[c]) + b1) ----
__global__ __launch_bounds__(256)
void gcn_gather(const float* __restrict__ b1) {
    int t = blockIdx.x * blockDim.x + threadIdx.x;
    int node = t >> 5, lane = t & 31;
    if (node >= N_NODES) return;
    float acc = g_xws[(size_t)node * H1 + lane];   // self-loop term (dis[n]*xw[n])
    int s = g_off[node], e = g_off[node + 1];
    for (int base = s; base < e; base += 32) {
        int cj = (base + lane < e) ? g_csr[base + lane] : 0;
        int m = min(e - base, 32);
        for (int i = 0; i < m; i++) {
            int c = __shfl_sync(0xffffffffu, cj, i);
            acc += g_xws[(size_t)c * H1 + lane];
        }
    }
    g_h[(size_t)node * H1 + lane] = fmaxf(g_dis[node] * acc + b1[lane], 0.0f);
}

// ---------------- K6: SAGE gather (warp/node): agg[n] = sum h[c] ----------------
__global__ __launch_bounds__(256)
void sage_gather() {
    int t = blockIdx.x * blockDim.x + threadIdx.x;
    int node = t >> 5, lane = t & 31;
    if (node >= N_NODES) return;
    float acc = 0.0f;
    int s = g_off[node], e = g_off[node + 1];
    for (int base = s; base < e; base += 32) {
        int cj = (base + lane < e) ? g_csr[base + lane] : 0;
        int m = min(e - base, 32);
        for (int i = 0; i < m; i++) {
            int c = __shfl_sync(0xffffffffu, cj, i);
            acc += g_h[(size_t)c * H1 + lane];
        }
    }
    g_agg[(size_t)node * H1 + lane] = acc;
}

// ---------------- K7: head ----------------
__global__ __launch_bounds__(256)
void final_kernel(const float* __restrict__ Wl, const float* __restrict__ bl,
                  const float* __restrict__ Wr, const float* __restrict__ br,
                  const float* __restrict__ W3, const float* __restrict__ b3,
                  float* __restrict__ out) {
    __shared__ float sWl[H1 * H2], sWr[H1 * H2], sW3[H2 * C_OUT];
    __shared__ float sbl[H2], sbr[H2], sb3[C_OUT];
    for (int i = threadIdx.x; i < H1 * H2; i += 256) { sWl[i] = Wl[i]; sWr[i] = Wr[i]; }
    if (threadIdx.x < H2 * C_OUT) sW3[threadIdx.x] = W3[threadIdx.x];
    if (threadIdx.x < H2) { sbl[threadIdx.x] = bl[threadIdx.x]; sbr[threadIdx.x] = br[threadIdx.x]; }
    if (threadIdx.x < C_OUT) sb3[threadIdx.x] = b3[threadIdx.x];
    __syncthreads();

    int n = blockIdx.x * blockDim.x + threadIdx.x;
    if (n >= N_NODES) return;

    float h[H1], ag[H1];
    const float4* hp = (const float4*)&g_h[(size_t)n * H1];
    const float4* ap = (const float4*)&g_agg[(size_t)n * H1];
#pragma unroll
    for (int i = 0; i < H1 / 4; i++) {
        float4 v = hp[i];
        h[i * 4 + 0] = v.x; h[i * 4 + 1] = v.y; h[i * 4 + 2] = v.z; h[i * 4 + 3] = v.w;
        float4 a = ap[i];
        ag[i * 4 + 0] = a.x; ag[i * 4 + 1] = a.y; ag[i * 4 + 2] = a.z; ag[i * 4 + 3] = a.w;
    }
    float cnt = (float)g_cnt_i[n];
    float cs = (cnt > 0.0f) ? (1.0f / cnt) : 0.0f;
#pragma unroll
    for (int k = 0; k < H1; k++) ag[k] *= cs;

    float o[H2];
    float ss = 0.0f;
#pragma unroll
    for (int j = 0; j < H2; j++) {
        float v = sbl[j] + sbr[j];
#pragma unroll
        for (int k = 0; k < H1; k++)
            v += h[k] * sWl[k * H2 + j] + ag[k] * sWr[k * H2 + j];
        v = fmaxf(v, 0.0f);
        o[j] = v;
        ss += v * v;
    }
    float inv = 1.0f / (sqrtf(ss) + 1e-6f);
#pragma unroll
    for (int j = 0; j < H2; j++) o[j] *= inv;

    float lg[C_OUT];
    float m = -1e30f;
#pragma unroll
    for (int j = 0; j < C_OUT; j++) {
        float v = sb3[j];
#pragma unroll
        for (int k = 0; k < H2; k++) v += o[k] * sW3[k * C_OUT + j];
        lg[j] = v;
        m = fmaxf(m, v);
    }
    float es = 0.0f;
#pragma unroll
    for (int j = 0; j < C_OUT; j++) { lg[j] = expf(lg[j] - m); es += lg[j]; }
    float invs = 1.0f / es;
#pragma unroll
    for (int j = 0; j < C_OUT; j++) out[(size_t)n * C_OUT + j] = lg[j] * invs;
}

// ---------------- launch ----------------
extern "C" void kernel_launch(void* const* d_in, const int* in_sizes, int n_in,
                              void* d_out, int out_size) {
    const float* x  = (const float*)d_in[0];
    const int*   ei = (const int*)d_in[1];   // int32 or int64 (autodetected)
    const float* W1 = (const float*)d_in[2];
    const float* b1 = (const float*)d_in[3];
    const float* Wl = (const float*)d_in[4];
    const float* bl = (const float*)d_in[5];
    const float* Wr = (const float*)d_in[6];
    const float* br = (const float*)d_in[7];
    const float* W3 = (const float*)d_in[8];
    const float* b3 = (const float*)d_in[9];
    float* out = (float*)d_out;

    init_kernel<<<(N_NODES + 255) / 256, 256>>>(ei);      // idx 0 (also detects dtype)
    hist_kernel<<<(E_EDGES + 255) / 256, 256>>>(ei);      // idx 1
    scan_kernel<<<1, 1024>>>();                           // idx 2
    gemm_kernel<<<N_NODES / BM, 128>>>(x, W1);            // idx 3 <- ncu captures this
    place_kernel<<<(E_EDGES + 255) / 256, 256>>>(ei);     // idx 4
    gcn_gather<<<(N_NODES * 32) / 256, 256>>>(b1);        // idx 5
    sage_gather<<<(N_NODES * 32) / 256, 256>>>();         // idx 6
    final_kernel<<<(N_NODES + 255) / 256, 256>>>(Wl, bl, Wr, br, W3, b3, out);
}

// round 13
// speedup vs baseline: 1.0596x; 1.0314x over previous
#include <cuda_runtime.h>
#include <math.h>

#define N_NODES 12288
#define F_IN    1433
#define E_EDGES 196608
#define H1      32
#define H2      16
#define C_OUT   7

// ---------------- scratch (static __device__, no allocations) ----------------
__device__ __align__(16) float g_xws[N_NODES * H1];  // dis[n] * (x @ W1)[n]
__device__ __align__(16) float g_h[N_NODES * H1];    // GCN output (post relu)
__device__ __align__(16) float g_agg[N_NODES * H1];  // SAGE neighbor sum
__device__ float g_dis[N_NODES];                 // (1+deg)^-0.5
__device__ __align__(16) int g_cnt_i[N_NODES];   // out-count over ei0 (SAGE denominator)
__device__ int   g_deg_i[N_NODES];               // in-count over ei1 (GCN degree)
__device__ int   g_off[N_NODES + 1];             // CSR row offsets (by r = ei0)
__device__ int   g_cur[N_NODES];                 // placement cursors
__device__ int   g_csr[E_EDGES];                 // CSR column indices (c = ei1)
__device__ int   g_is64;                         // edge_index dtype flag

__device__ __forceinline__ int edge_at(const int* ei32, int is64, int idx) {
    if (is64) return __ldg(&ei32[2 * idx]);  // little-endian low word of int64
    return __ldg(&ei32[idx]);
}

// ---------------- K0: init counters + detect dtype (fused) ----------------
__global__ void init_kernel(const int* __restrict__ ei32) {
    int idx = blockIdx.x * blockDim.x + threadIdx.x;
    if (idx < N_NODES) { g_cnt_i[idx] = 0; g_deg_i[idx] = 0; g_cur[idx] = 0; }
    if (idx == 0) {
        int any = 0;
        for (int k = 0; k < 256; k++) any |= ei32[2 * k + 1];
        g_is64 = (any == 0) ? 1 : 0;
    }
}

// ---------------- K1: degree / count histogram (int) ----------------
__global__ void hist_kernel(const int* __restrict__ ei32) {
    int e = blockIdx.x * blockDim.x + threadIdx.x;
    if (e < E_EDGES) {
        int is64 = g_is64;
        int r = edge_at(ei32, is64, e);
        int c = edge_at(ei32, is64, E_EDGES + e);
        if ((unsigned)r < N_NODES) atomicAdd(&g_cnt_i[r], 1);
        if ((unsigned)c < N_NODES) atomicAdd(&g_deg_i[c], 1);
    }
}

// ---------------- K2: exclusive scan of cnt -> CSR offsets (1 block, shfl) ----
__global__ __launch_bounds__(1024) void scan_kernel() {
    __shared__ int wsum[32];
    __shared__ int wexcl[32];
    int t = threadIdx.x, lane = t & 31, wid = t >> 5;
    int4 a = *reinterpret_cast<const int4*>(&g_cnt_i[t * 12]);
    int4 b = *reinterpret_cast<const int4*>(&g_cnt_i[t * 12 + 4]);
    int4 c = *reinterpret_cast<const int4*>(&g_cnt_i[t * 12 + 8]);
    int v[12] = {a.x, a.y, a.z, a.w, b.x, b.y, b.z, b.w, c.x, c.y, c.z, c.w};
    int pre[12];
    int s = 0;
#pragma unroll
    for (int i = 0; i < 12; i++) { pre[i] = s; s += v[i]; }
    int inc = s;
#pragma unroll
    for (int d = 1; d < 32; d <<= 1) {
        int u = __shfl_up_sync(0xffffffffu, inc, d);
        if (lane >= d) inc += u;
    }
    if (lane == 31) wsum[wid] = inc;
    __syncthreads();
    if (wid == 0) {
        int w = wsum[lane];
        int winc = w;
#pragma unroll
        for (int d = 1; d < 32; d <<= 1) {
            int u = __shfl_up_sync(0xffffffffu, winc, d);
            if (lane >= d) winc += u;
        }
        wexcl[lane] = winc - w;
    }
    __syncthreads();
    int base = wexcl[wid] + (inc - s);
#pragma unroll
    for (int i = 0; i < 12; i++) g_off[t * 12 + i] = base + pre[i];
    if (t == 1023) g_off[N_NODES] = base + s;
}

// ---------------- K3: xw = x @ W1 ; epilogue: g_xws = dis*xw, g_dis ----------
// BM=32, BK=64, 256 threads, 1 row x 4 cols per thread. grid = 384.
// Register-prefetch double buffering over 23 K-tiles.
#define BM  32
#define BKT 64
#define XS_STRIDE 68
__global__ __launch_bounds__(256)
void gemm_kernel(const float* __restrict__ x, const float* __restrict__ W1) {
    __shared__ float xs[2][BM * XS_STRIDE];   // 2 x 32 x 68 floats
    __shared__ float ws[2][BKT * H1];         // 2 x 64 x 32 floats

    const int tid = threadIdx.x;
    const int rowBase = blockIdx.x * BM;
    const int tx4 = (tid & 7) * 4;   // output cols tx4..tx4+3
    const int row = tid >> 3;        // output row 0..31

    // gmem load indices (8 floats each for xs and ws per thread)
    // xs flat: f = tid + i*256 ; xr = f>>6 (row), xk = f&63
    // ws flat: f = tid + i*256 ; wk = f>>5, wc = f&31
    const int nT = (F_IN + BKT - 1) / BKT;  // 23

    float rx[8], rw[8];
    // prologue: load tile 0
    {
        const int kBase = 0;
#pragma unroll
        for (int i = 0; i < 8; i++) {
            int f = tid + i * 256;
            int xr = f >> 6, xk = f & 63;
            rx[i] = x[(size_t)(rowBase + xr) * F_IN + (kBase + xk)];
            int wk = f >> 5, wc = f & 31;
            rw[i] = W1[(size_t)(kBase + wk) * H1 + wc];
        }
#pragma unroll
        for (int i = 0; i < 8; i++) {
            int f = tid + i * 256;
            int xr = f >> 6, xk = f & 63;
            xs[0][xr * XS_STRIDE + xk] = rx[i];
            int wk = f >> 5, wc = f & 31;
            ws[0][wk * H1 + wc] = rw[i];
        }
    }

    float acc0 = 0.f, acc1 = 0.f, acc2 = 0.f, acc3 = 0.f;

    for (int kt = 0; kt < nT; kt++) {
        __syncthreads();   // buffer kt ready
        const int buf = kt & 1;

        // prefetch tile kt+1 into registers (overlaps with compute below)
        const int kNext = (kt + 1) * BKT;
        if (kt + 1 < nT) {
#pragma unroll
            for (int i = 0; i < 8; i++) {
                int f = tid + i * 256;
                int xr = f >> 6, xk = f & 63;
                int kg = kNext + xk;
                rx[i] = (kg < F_IN) ? x[(size_t)(rowBase + xr) * F_IN + kg] : 0.0f;
                int wk = f >> 5, wc = f & 31;
                int kw = kNext + wk;
                rw[i] = (kw < F_IN) ? W1[(size_t)kw * H1 + wc] : 0.0f;
            }
        }

        // compute on buffer kt
        const float* xrow = &xs[buf][row * XS_STRIDE];
        const float* wbase = &ws[buf][tx4];
#pragma unroll 16
        for (int k = 0; k < BKT; k++) {
            float a = xrow[k];
            float4 b = *reinterpret_cast<const float4*>(&wbase[k * H1]);
            acc0 += a * b.x; acc1 += a * b.y; acc2 += a * b.z; acc3 += a * b.w;
        }

        __syncthreads();   // everyone done reading buffer kt^? (before overwrite of other buf)
        if (kt + 1 < nT) {
            const int nbuf = (kt + 1) & 1;
#pragma unroll
            for (int i = 0; i < 8; i++) {
                int f = tid + i * 256;
                int xr = f >> 6, xk = f & 63;
                xs[nbuf][xr * XS_STRIDE + xk] = rx[i];
                int wk = f >> 5, wc = f & 31;
                ws[nbuf][wk * H1 + wc] = rw[i];
            }
        }
    }

    // epilogue: dis = (1+deg)^-1/2 ; g_xws = dis * acc ; g_dis
    int grow = rowBase + row;
    float dis = rsqrtf(1.0f + (float)g_deg_i[grow]);
    if (tx4 == 0) g_dis[grow] = dis;
    float4 outv = make_float4(dis * acc0, dis * acc1, dis * acc2, dis * acc3);
    *reinterpret_cast<float4*>(&g_xws[(size_t)grow * H1 + tx4]) = outv;
}

// ---------------- K4: CSR placement ----------------
__global__ void place_kernel(const int* __restrict__ ei32) {
    int e = blockIdx.x * blockDim.x + threadIdx.x;
    if (e >= E_EDGES) return;
    int is64 = g_is64;
    int r = edge_at(ei32, is64, e);
    int c = edge_at(ei32, is64, E_EDGES + e);
    if ((unsigned)r < N_NODES) {
        c = min(max(c, 0), N_NODES - 1);
        int p = atomicAdd(&g_cur[r], 1);
        g_csr[g_off[r] + p] = c;
    }
}

// ---------------- K5: GCN gather: h = relu(dis[n]*(self + sum xws[c]) + b1) ----
__global__ __launch_bounds__(256)
void gcn_gather(const float* __restrict__ b1) {
    int t = blockIdx.x * blockDim.x + threadIdx.x;
    int node = t >> 5, lane = t & 31;
    if (node >= N_NODES) return;
    float acc = g_xws[(size_t)node * H1 + lane];   // self-loop (dis[n]*xw[n])
    int s = g_off[node], e = g_off[node + 1];
    for (int base = s; base < e; base += 32) {
        int cj = (base + lane < e) ? g_csr[base + lane] : 0;
        int m = min(e - base, 32);
        for (int i = 0; i < m; i++) {
            int c = __shfl_sync(0xffffffffu, cj, i);
            acc += g_xws[(size_t)c * H1 + lane];
        }
    }
    g_h[(size_t)node * H1 + lane] = fmaxf(g_dis[node] * acc + b1[lane], 0.0f);
}

// ---------------- K6: SAGE gather: agg[n] = sum h[c] ----------------
__global__ __launch_bounds__(256)
void sage_gather() {
    int t = blockIdx.x * blockDim.x + threadIdx.x;
    int node = t >> 5, lane = t & 31;
    if (node >= N_NODES) return;
    float acc = 0.0f;
    int s = g_off[node], e = g_off[node + 1];
    for (int base = s; base < e; base += 32) {
        int cj = (base + lane < e) ? g_csr[base + lane] : 0;
        int m = min(e - base, 32);
        for (int i = 0; i < m; i++) {
            int c = __shfl_sync(0xffffffffu, cj, i);
            acc += g_h[(size_t)c * H1 + lane];
        }
    }
    g_agg[(size_t)node * H1 + lane] = acc;
}

// ---------------- K7: head ----------------
__global__ __launch_bounds__(256)
void final_kernel(const float* __restrict__ Wl, const float* __restrict__ bl,
                  const float* __restrict__ Wr, const float* __restrict__ br,
                  const float* __restrict__ W3, const float* __restrict__ b3,
                  float* __restrict__ out) {
    __shared__ float sWl[H1 * H2], sWr[H1 * H2], sW3[H2 * C_OUT];
    __shared__ float sbl[H2], sbr[H2], sb3[C_OUT];
    for (int i = threadIdx.x; i < H1 * H2; i += 256) { sWl[i] = Wl[i]; sWr[i] = Wr[i]; }
    if (threadIdx.x < H2 * C_OUT) sW3[threadIdx.x] = W3[threadIdx.x];
    if (threadIdx.x < H2) { sbl[threadIdx.x] = bl[threadIdx.x]; sbr[threadIdx.x] = br[threadIdx.x]; }
    if (threadIdx.x < C_OUT) sb3[threadIdx.x] = b3[threadIdx.x];
    __syncthreads();

    int n = blockIdx.x * blockDim.x + threadIdx.x;
    if (n >= N_NODES) return;

    float h[H1], ag[H1];
    const float4* hp = (const float4*)&g_h[(size_t)n * H1];
    const float4* ap = (const float4*)&g_agg[(size_t)n * H1];
#pragma unroll
    for (int i = 0; i < H1 / 4; i++) {
        float4 v = hp[i];
        h[i * 4 + 0] = v.x; h[i * 4 + 1] = v.y; h[i * 4 + 2] = v.z; h[i * 4 + 3] = v.w;
        float4 a = ap[i];
        ag[i * 4 + 0] = a.x; ag[i * 4 + 1] = a.y; ag[i * 4 + 2] = a.z; ag[i * 4 + 3] = a.w;
    }
    float cnt = (float)g_cnt_i[n];
    float cs = (cnt > 0.0f) ? (1.0f / cnt) : 0.0f;
#pragma unroll
    for (int k = 0; k < H1; k++) ag[k] *= cs;

    float o[H2];
    float ss = 0.0f;
#pragma unroll
    for (int j = 0; j < H2; j++) {
        float v = sbl[j] + sbr[j];
#pragma unroll
        for (int k = 0; k < H1; k++)
            v += h[k] * sWl[k * H2 + j] + ag[k] * sWr[k * H2 + j];
        v = fmaxf(v, 0.0f);
        o[j] = v;
        ss += v * v;
    }
    float inv = 1.0f / (sqrtf(ss) + 1e-6f);
#pragma unroll
    for (int j = 0; j < H2; j++) o[j] *= inv;

    float lg[C_OUT];
    float m = -1e30f;
#pragma unroll
    for (int j = 0; j < C_OUT; j++) {
        float v = sb3[j];
#pragma unroll
        for (int k = 0; k < H2; k++) v += o[k] * sW3[k * C_OUT + j];
        lg[j] = v;
        m = fmaxf(m, v);
    }
    float es = 0.0f;
#pragma unroll
    for (int j = 0; j < C_OUT; j++) { lg[j] = expf(lg[j] - m); es += lg[j]; }
    float invs = 1.0f / es;
#pragma unroll
    for (int j = 0; j < C_OUT; j++) out[(size_t)n * C_OUT + j] = lg[j] * invs;
}

// ---------------- launch ----------------
extern "C" void kernel_launch(void* const* d_in, const int* in_sizes, int n_in,
                              void* d_out, int out_size) {
    const float* x  = (const float*)d_in[0];
    const int*   ei = (const int*)d_in[1];   // int32 or int64 (autodetected)
    const float* W1 = (const float*)d_in[2];
    const float* b1 = (const float*)d_in[3];
    const float* Wl = (const float*)d_in[4];
    const float* bl = (const float*)d_in[5];
    const float* Wr = (const float*)d_in[6];
    const float* br = (const float*)d_in[7];
    const float* W3 = (const float*)d_in[8];
    const float* b3 = (const float*)d_in[9];
    float* out = (float*)d_out;

    init_kernel<<<(N_NODES + 255) / 256, 256>>>(ei);      // idx 0
    hist_kernel<<<(E_EDGES + 255) / 256, 256>>>(ei);      // idx 1
    scan_kernel<<<1, 1024>>>();                           // idx 2
    gemm_kernel<<<N_NODES / BM, 256>>>(x, W1);            // idx 3 <- ncu captures this
    place_kernel<<<(E_EDGES + 255) / 256, 256>>>(ei);     // idx 4
    gcn_gather<<<(N_NODES * 32) / 256, 256>>>(b1);        // idx 5
    sage_gather<<<(N_NODES * 32) / 256, 256>>>();         // idx 6
    final_kernel<<<(N_NODES + 255) / 256, 256>>>(Wl, bl, Wr, br, W3, b3, out);
}